// round 12
// baseline (speedup 1.0000x reference)
#include <cuda_runtime.h>
#include <cuda_fp16.h>

#define MAX_NODES (1 << 17)
// Zero-initialized at module load. INVARIANT: zero at entry of every
// kernel_launch call; mlp_kernel re-zeroes each element after consuming it.
__device__ float g_lf[MAX_NODES];

__constant__ float cw1[32];
__constant__ float cb1[16];
__constant__ float cw2[256];
__constant__ float cb2[16];

// Persistent edge kernel. Each CTA: (a) detects index width locally,
// (b) converts x -> fp16 into its own smem table, (c) streams edges doing
// S[row] += (float)x_h[col].  512 threads, 4 edges/thread (no spills).
__global__ void __launch_bounds__(512, 1)
edge_kernel(const float* __restrict__ x,
            const void* __restrict__ ei, long long E, int n) {
    extern __shared__ __half sx[];
    __shared__ int s_flag[4];

    // --- local index-width detect: warps 0-3 scan first 128 int64 views ---
    if (threadIdx.x < 128) {
        const long long* p = (const long long*)ei;
        long long v = p[threadIdx.x];
        int is_bad = (v < 0 || v >= (long long)n) ? 1 : 0;
        unsigned m = __ballot_sync(0xFFFFFFFFu, is_bad);
        if ((threadIdx.x & 31) == 0) s_flag[threadIdx.x >> 5] = (m != 0);
    }

    // --- convert x (fp32, L2-resident) into smem fp16 table ---
    {
        int nv4 = n >> 2;
        const float4* x4 = reinterpret_cast<const float4*>(x);
        __half2* sx2 = reinterpret_cast<__half2*>(sx);
        for (int i = threadIdx.x; i < nv4; i += blockDim.x) {
            float4 v = x4[i];
            sx2[i * 2]     = __floats2half2_rn(v.x, v.y);
            sx2[i * 2 + 1] = __floats2half2_rn(v.z, v.w);
        }
        for (int i = (nv4 << 2) + threadIdx.x; i < n; i += blockDim.x)
            sx[i] = __float2half(x[i]);
    }
    __syncthreads();

    int is32 = s_flag[0] | s_flag[1] | s_flag[2] | s_flag[3];

    long long nvec = E >> 2;
    long long stride = (long long)gridDim.x * blockDim.x;

    for (long long t = (long long)blockIdx.x * blockDim.x + threadIdx.x;
         t < nvec; t += stride) {
        long long base = t << 2;
        int r[4], c[4];
        if (is32) {
            const int* rows = (const int*)ei;
            const int* cols = rows + E;
            int4 ra = *reinterpret_cast<const int4*>(rows + base);
            int4 ca = *reinterpret_cast<const int4*>(cols + base);
            r[0] = ra.x; r[1] = ra.y; r[2] = ra.z; r[3] = ra.w;
            c[0] = ca.x; c[1] = ca.y; c[2] = ca.z; c[3] = ca.w;
        } else {
            const long long* rows = (const long long*)ei;
            const long long* cols = rows + E;
            longlong2 ra = *reinterpret_cast<const longlong2*>(rows + base);
            longlong2 rb = *reinterpret_cast<const longlong2*>(rows + base + 2);
            longlong2 ca = *reinterpret_cast<const longlong2*>(cols + base);
            longlong2 cb = *reinterpret_cast<const longlong2*>(cols + base + 2);
            r[0] = (int)ra.x; r[1] = (int)ra.y; r[2] = (int)rb.x; r[3] = (int)rb.y;
            c[0] = (int)ca.x; c[1] = (int)ca.y; c[2] = (int)cb.x; c[3] = (int)cb.y;
        }
        float v[4];
#pragma unroll
        for (int k = 0; k < 4; k++) v[k] = __half2float(sx[c[k]]);
#pragma unroll
        for (int k = 0; k < 4; k++) atomicAdd(&g_lf[r[k]], v[k]);
    }

    // tail (E not divisible by 4)
    if (blockIdx.x == 0 && threadIdx.x == 0) {
        for (long long e = nvec << 2; e < E; e++) {
            int rr, cc;
            if (is32) {
                const int* rows = (const int*)ei;
                rr = rows[e]; cc = rows[E + e];
            } else {
                const long long* rows = (const long long*)ei;
                rr = (int)rows[e]; cc = (int)rows[E + e];
            }
            atomicAdd(&g_lf[rr], __half2float(sx[cc]));
        }
    }
}

// MLP with __constant__ weights: no smem staging, no __syncthreads.
// Two nodes per thread (i, i+blockDim) for constant-read amortization + ILP.
// lf = x[i] * S[i] (factored multiply). Resets g_lf after consuming it
// to maintain the zero-invariant for the next graph replay.
__global__ void mlp_kernel(const float* __restrict__ x,
                           float* __restrict__ out, int n) {
    int ia = blockIdx.x * (blockDim.x * 2) + threadIdx.x;
    int ib = ia + blockDim.x;
    bool vb = (ib < n);
    if (ia >= n) return;

    float xa = x[ia];
    float lfa = xa * g_lf[ia];
    g_lf[ia] = 0.0f;
    float xb = 0.f, lfb = 0.f;
    if (vb) {
        xb = x[ib];
        lfb = xb * g_lf[ib];
        g_lf[ib] = 0.0f;
    }

    float ha[16], hb[16];
#pragma unroll
    for (int j = 0; j < 16; j++) {
        float w0 = cw1[2 * j], w1v = cw1[2 * j + 1], bj = cb1[j];
        ha[j] = fmaxf(fmaf(xa, w0, fmaf(lfa, w1v, bj)), 0.0f);
        hb[j] = fmaxf(fmaf(xb, w0, fmaf(lfb, w1v, bj)), 0.0f);
    }

    float oa[16], ob[16];
#pragma unroll
    for (int k = 0; k < 16; k++) {
        float sa = cb2[k], sb = sa;
#pragma unroll
        for (int j = 0; j < 16; j++) {
            float w = cw2[k * 16 + j];
            sa = fmaf(ha[j], w, sa);
            sb = fmaf(hb[j], w, sb);
        }
        oa[k] = fmaxf(sa, 0.0f);
        ob[k] = fmaxf(sb, 0.0f);
    }

    float4* o4a = reinterpret_cast<float4*>(out + (size_t)ia * 16);
    o4a[0] = make_float4(oa[0],  oa[1],  oa[2],  oa[3]);
    o4a[1] = make_float4(oa[4],  oa[5],  oa[6],  oa[7]);
    o4a[2] = make_float4(oa[8],  oa[9],  oa[10], oa[11]);
    o4a[3] = make_float4(oa[12], oa[13], oa[14], oa[15]);
    if (vb) {
        float4* o4b = reinterpret_cast<float4*>(out + (size_t)ib * 16);
        o4b[0] = make_float4(ob[0],  ob[1],  ob[2],  ob[3]);
        o4b[1] = make_float4(ob[4],  ob[5],  ob[6],  ob[7]);
        o4b[2] = make_float4(ob[8],  ob[9],  ob[10], ob[11]);
        o4b[3] = make_float4(ob[12], ob[13], ob[14], ob[15]);
    }
}

extern "C" void kernel_launch(void* const* d_in, const int* in_sizes, int n_in,
                              void* d_out, int out_size) {
    const float* x  = (const float*)d_in[0];
    const void*  ei = d_in[1];
    const float* w1 = (const float*)d_in[2];
    const float* b1 = (const float*)d_in[3];
    const float* w2 = (const float*)d_in[4];
    const float* b2 = (const float*)d_in[5];
    float*       out = (float*)d_out;

    int n = in_sizes[0];                        // x is [N, 1]
    long long E = (long long)in_sizes[1] / 2;   // edge_index is [2, E]

    size_t smem_bytes = ((size_t)n * 2 + 15) & ~(size_t)15;
    cudaFuncSetAttribute(edge_kernel,
                         cudaFuncAttributeMaxDynamicSharedMemorySize,
                         (int)smem_bytes);

    // D2D async copies into __constant__ — capture-legal, overlap with edge.
    cudaMemcpyToSymbolAsync(cw1, w1,  32 * sizeof(float), 0, cudaMemcpyDeviceToDevice);
    cudaMemcpyToSymbolAsync(cb1, b1,  16 * sizeof(float), 0, cudaMemcpyDeviceToDevice);
    cudaMemcpyToSymbolAsync(cw2, w2, 256 * sizeof(float), 0, cudaMemcpyDeviceToDevice);
    cudaMemcpyToSymbolAsync(cb2, b2,  16 * sizeof(float), 0, cudaMemcpyDeviceToDevice);

    edge_kernel<<<148, 512, smem_bytes>>>(x, ei, E, n);

    int mlp_tpb = 128;   // 256 nodes per block -> 391 blocks
    int mlp_blocks = (n + mlp_tpb * 2 - 1) / (mlp_tpb * 2);
    mlp_kernel<<<mlp_blocks, mlp_tpb>>>(x, out, n);
}